// round 7
// baseline (speedup 1.0000x reference)
#include <cuda_runtime.h>
#include <cuda_fp16.h>
#include <cstdint>

typedef unsigned long long ULL;
typedef uint32_t U32;

#define C_DIMM 256
#define L_DIMM 2048
#define K_CB   8192
#define M_DIM  16384
#define EMB_N  4194304

#define BM 32
#define NTILE 64          // 8192/128
#define NCH 8             // 256/32

__device__ float g_csq[K_CB];
__device__ float g_cmax[1];
__device__ int   g_flag[M_DIM];
__device__ int   g_ncand[M_DIM];
__device__ int   g_cand[M_DIM * 8];
__device__ int   g_code[M_DIM];
__device__ float g_partial[EMB_N / 256];

// ---------------- helpers ----------------
__device__ __forceinline__ U32 pack2(float a, float b) {
    __half2 h = __floats2half2_rn(a, b);
    return *(U32*)&h;
}
__device__ __forceinline__ ULL makeKey(float s, int gk) {
    unsigned u = __float_as_uint(s);
    u = (u & 0x80000000u) ? ~u : (u | 0x80000000u);
    return ((ULL)u << 32) | (unsigned)(0xFFFFFFFFu - (unsigned)gk);
}
__device__ __forceinline__ float keyVal(ULL k) {
    unsigned v = (unsigned)(k >> 32);
    v = (v & 0x80000000u) ? (v ^ 0x80000000u) : ~v;
    return __uint_as_float(v);
}
__device__ __forceinline__ int keyIdx(ULL k) {
    return (int)(0xFFFFFFFFu - (unsigned)(k & 0xffffffffu));
}
__device__ __forceinline__ ULL maxk(ULL a, ULL b) { return a > b ? a : b; }

__device__ __forceinline__ void ins6(ULL* t, ULL k) {
    if (k > t[5]) {
        t[5] = k; ULL z;
        if (t[5] > t[4]) { z = t[4]; t[4] = t[5]; t[5] = z;
        if (t[4] > t[3]) { z = t[3]; t[3] = t[4]; t[4] = z;
        if (t[3] > t[2]) { z = t[2]; t[2] = t[3]; t[3] = z;
        if (t[2] > t[1]) { z = t[1]; t[1] = t[2]; t[2] = z;
        if (t[1] > t[0]) { z = t[0]; t[0] = t[1]; t[1] = z; } } } } }
    }
}

// ---------------- kernel 1: codebook squared norms ----------------
__global__ void csq_kernel(const float* __restrict__ cb) {
    int k = blockIdx.x * 8 + (threadIdx.x >> 5);
    int lane = threadIdx.x & 31;
    const float* row = cb + (size_t)k * C_DIMM;
    float s = 0.0f;
    #pragma unroll
    for (int c = lane; c < C_DIMM; c += 32) { float v = row[c]; s = fmaf(v, v, s); }
    #pragma unroll
    for (int o = 16; o > 0; o >>= 1) s += __shfl_xor_sync(0xffffffffu, s, o);
    if (lane == 0) g_csq[k] = s;
}

// ---------------- kernel 2: max codebook norm ----------------
__global__ void cmax_kernel() {
    __shared__ float sr[256];
    float m = 0.0f;
    for (int i = threadIdx.x; i < K_CB; i += 256) m = fmaxf(m, g_csq[i]);
    sr[threadIdx.x] = m;
    __syncthreads();
    #pragma unroll
    for (int o = 128; o > 0; o >>= 1) {
        if (threadIdx.x < o) sr[threadIdx.x] = fmaxf(sr[threadIdx.x], sr[threadIdx.x + o]);
        __syncthreads();
    }
    if (threadIdx.x == 0) g_cmax[0] = sqrtf(sr[0]);
}

// ---------------- kernel 3: HFMA2 fp16 GEMM + guaranteed argmax ----------------
// scores s_k = csq_k - 2*dot; fp16 k-pair chains (len 16) drained to fp32 per chunk.
__global__ __launch_bounds__(256, 2) void argmax_hf(const float* __restrict__ x,
                                                    const float* __restrict__ cb) {
    __shared__ U32 As[2][16 * 34];        // [buf][kp*34 + m]  (m<32, pad 2)
    __shared__ U32 Bs[2][16 * 132];       // [buf][kp*132 + n] (n<128, pad 4)
    __shared__ float xns[BM];

    const int tid = threadIdx.x;
    const int tx = tid & 15;
    const int ty = tid >> 4;
    const int ty2 = ty * 2;

    const int rowBase = blockIdx.x * BM;
    const int bidx = rowBase >> 11, l0 = rowBase & 2047;
    const float* xb = x + (size_t)bidx * (C_DIMM * L_DIMM) + l0;

    // exact per-row fp32 norms (for the error margin)
    if (tid < BM) {
        float s = 0.0f;
        const float* xr = xb + tid;
        for (int c = 0; c < C_DIMM; ++c) { float v = xr[(size_t)c * L_DIMM]; s = fmaf(v, v, s); }
        xns[tid] = sqrtf(s);
    }

    // loader mappings
    const int kpA = tid >> 4;             // 0..15
    const int mA  = (tid & 15) * 2;       // 0..30
    const int nB  = tid & 127;            // codeword in tile
    const int hB  = tid >> 7;             // k-half (16 c)

    // preload chunk 0 (tile 0) into buf 0
    {
        float2 u = *(const float2*)(xb + (size_t)(2 * kpA) * L_DIMM + mA);
        float2 v = *(const float2*)(xb + (size_t)(2 * kpA + 1) * L_DIMM + mA);
        As[0][kpA * 34 + mA]     = pack2(u.x, v.x);
        As[0][kpA * 34 + mA + 1] = pack2(u.y, v.y);
        const float* src = cb + (size_t)nB * C_DIMM + hB * 16;
        #pragma unroll
        for (int q = 0; q < 4; ++q) {
            float4 f = *(const float4*)(src + q * 4);
            int kp = hB * 8 + q * 2;
            Bs[0][kp * 132 + nB]       = pack2(f.x, f.y);
            Bs[0][(kp + 1) * 132 + nB] = pack2(f.z, f.w);
        }
    }
    __syncthreads();

    __half2 acc16[2][8];
    float acc32[2][8];
    ULL run[2][6];
    #pragma unroll
    for (int i = 0; i < 2; ++i) {
        #pragma unroll
        for (int j = 0; j < 8; ++j) { acc16[i][j] = __floats2half2_rn(0.f, 0.f); acc32[i][j] = 0.0f; }
        #pragma unroll
        for (int s = 0; s < 6; ++s) run[i][s] = 0ULL;
    }

    for (int gi = 0; gi < NTILE * NCH; ++gi) {
        const int kt = gi >> 3, ch = gi & 7, buf = gi & 1;
        const bool more = (gi + 1 < NTILE * NCH);

        // stage next chunk into registers (packed immediately -> fewer regs)
        U32 sa0 = 0, sa1 = 0, sb[8];
        if (more) {
            const int nkt = (gi + 1) >> 3, nch = (gi + 1) & 7;
            const int ck = nch * 32;
            float2 u = *(const float2*)(xb + (size_t)(ck + 2 * kpA) * L_DIMM + mA);
            float2 v = *(const float2*)(xb + (size_t)(ck + 2 * kpA + 1) * L_DIMM + mA);
            sa0 = pack2(u.x, v.x);
            sa1 = pack2(u.y, v.y);
            const float* src = cb + (size_t)(nkt * 128 + nB) * C_DIMM + ck + hB * 16;
            #pragma unroll
            for (int q = 0; q < 4; ++q) {
                float4 f = *(const float4*)(src + q * 4);
                sb[q * 2]     = pack2(f.x, f.y);
                sb[q * 2 + 1] = pack2(f.z, f.w);
            }
        }

        // compute 16 k-pairs from buf
        #pragma unroll
        for (int kp = 0; kp < 16; ++kp) {
            ULL ap = *(const ULL*)&As[buf][kp * 34 + ty2];
            __half2 a0 = *(__half2*)&ap;
            U32 ahi = (U32)(ap >> 32);
            __half2 a1 = *(__half2*)&ahi;
            #pragma unroll
            for (int p = 0; p < 4; ++p) {
                ULL bp = *(const ULL*)&Bs[buf][kp * 132 + 2 * tx + 32 * p];
                U32 bl = (U32)bp, bh = (U32)(bp >> 32);
                __half2 b0 = *(__half2*)&bl;
                __half2 b1 = *(__half2*)&bh;
                acc16[0][2 * p]     = __hfma2(a0, b0, acc16[0][2 * p]);
                acc16[0][2 * p + 1] = __hfma2(a0, b1, acc16[0][2 * p + 1]);
                acc16[1][2 * p]     = __hfma2(a1, b0, acc16[1][2 * p]);
                acc16[1][2 * p + 1] = __hfma2(a1, b1, acc16[1][2 * p + 1]);
            }
        }

        // drain fp16 chains (length 16) into fp32
        #pragma unroll
        for (int i = 0; i < 2; ++i)
            #pragma unroll
            for (int j = 0; j < 8; ++j) {
                float2 f = __half22float2(acc16[i][j]);
                acc32[i][j] += f.x + f.y;
                acc16[i][j] = __floats2half2_rn(0.f, 0.f);
            }

        if (more) {
            As[buf ^ 1][kpA * 34 + mA]     = sa0;
            As[buf ^ 1][kpA * 34 + mA + 1] = sa1;
            #pragma unroll
            for (int q = 0; q < 8; ++q)
                Bs[buf ^ 1][(hB * 8 + q) * 132 + nB] = sb[q];
        }
        __syncthreads();

        if (ch == 7) {  // tile finished: fold 16 scores into per-lane top-6
            const int kb = kt * 128 + 2 * tx;
            #pragma unroll
            for (int p = 0; p < 4; ++p) {
                float2 cq = __ldg((const float2*)&g_csq[kb + 32 * p]);
                #pragma unroll
                for (int i = 0; i < 2; ++i) {
                    float s0 = fmaf(-2.0f, acc32[i][2 * p], cq.x);
                    float s1 = fmaf(-2.0f, acc32[i][2 * p + 1], cq.y);
                    ins6(run[i], makeKey(s0, kb + 32 * p));
                    ins6(run[i], makeKey(s1, kb + 32 * p + 1));
                    acc32[i][2 * p] = 0.0f;
                    acc32[i][2 * p + 1] = 0.0f;
                }
            }
        }
    }

    // merge top-6 across the 16 tx lanes (xor stays within same-row group)
    #pragma unroll
    for (int off = 1; off <= 8; off <<= 1) {
        #pragma unroll
        for (int i = 0; i < 2; ++i) {
            ULL tmp[6];
            #pragma unroll
            for (int s = 0; s < 6; ++s) tmp[s] = __shfl_xor_sync(0xffffffffu, run[i][s], off);
            #pragma unroll
            for (int s = 0; s < 6; ++s) ins6(run[i], tmp[s]);
        }
    }

    if (tx == 0) {
        float cmaxv = g_cmax[0];
        #pragma unroll
        for (int i = 0; i < 2; ++i) {
            int rl = ty2 + i;
            int row = rowBase + rl;
            float marg = fmaf(xns[rl] * cmaxv, 0.0176f, 0.1f);  // 2E rigorous + slack
            float v0 = keyVal(run[i][0]);
            int c0 = keyIdx(run[i][0]);
            g_code[row] = c0;
            float v1 = keyVal(run[i][1]);
            float v5 = keyVal(run[i][5]);
            if (v0 - v1 > marg) {
                g_flag[row] = 0;                      // provably exact
            } else if (v0 - v5 <= marg) {
                g_flag[row] = 2;                      // rare: full exact rescan
            } else {
                int nc = 1;
                g_cand[row * 8] = c0;
                #pragma unroll
                for (int k = 1; k < 5; ++k) {
                    float vk = keyVal(run[i][k]);
                    if (v0 - vk <= marg) { g_cand[row * 8 + nc] = keyIdx(run[i][k]); ++nc; }
                }
                g_flag[row] = 1;
                g_ncand[row] = nc;
            }
        }
    }
}

// ---------------- kernel 4: exact-fp32 rescue for flagged rows ----------------
__global__ void rescue_kernel(const float* __restrict__ x, const float* __restrict__ cb) {
    __shared__ float xs[8][C_DIMM];
    int w = threadIdx.x >> 5, lane = threadIdx.x & 31;
    int row = blockIdx.x * 8 + w;
    int fl = g_flag[row];
    if (fl == 0) return;
    int b = row >> 11, l = row & 2047;
    const float* xr = x + (size_t)b * C_DIMM * L_DIMM + l;
    #pragma unroll
    for (int i = 0; i < 8; ++i) xs[w][lane + 32 * i] = xr[(size_t)(lane + 32 * i) * L_DIMM];
    __syncwarp();
    const float4* x4 = (const float4*)xs[w];
    ULL best = 0ULL;
    if (fl == 1) {
        int nc = g_ncand[row];
        if (lane < nc) {
            int k = g_cand[row * 8 + lane];
            const float4* cr = (const float4*)(cb + (size_t)k * C_DIMM);
            float d = 0.0f;
            #pragma unroll 8
            for (int i = 0; i < 64; ++i) {
                float4 a = x4[i], c = cr[i];
                d = fmaf(a.x, c.x, d); d = fmaf(a.y, c.y, d);
                d = fmaf(a.z, c.z, d); d = fmaf(a.w, c.w, d);
            }
            best = makeKey(fmaf(-2.0f, d, g_csq[k]), k);
        }
    } else {
        for (int k = lane; k < K_CB; k += 32) {
            const float4* cr = (const float4*)(cb + (size_t)k * C_DIMM);
            float d = 0.0f;
            #pragma unroll 8
            for (int i = 0; i < 64; ++i) {
                float4 a = x4[i], c = cr[i];
                d = fmaf(a.x, c.x, d); d = fmaf(a.y, c.y, d);
                d = fmaf(a.z, c.z, d); d = fmaf(a.w, c.w, d);
            }
            best = maxk(best, makeKey(fmaf(-2.0f, d, g_csq[k]), k));
        }
    }
    #pragma unroll
    for (int o = 16; o > 0; o >>= 1)
        best = maxk(best, __shfl_xor_sync(0xffffffffu, best, o));
    if (lane == 0 && best != 0ULL) g_code[row] = keyIdx(best);
}

// ---------------- output kernels ----------------
__global__ void code_cast_kernel(float* __restrict__ out_code) {
    int i = blockIdx.x * 256 + threadIdx.x;
    if (i < M_DIM) out_code[i] = (float)g_code[i];
}

__global__ void gather_loss_kernel(const float* __restrict__ x,
                                   const float* __restrict__ cb,
                                   float* __restrict__ emb_out) {
    __shared__ float sred[256];
    int idx = blockIdx.x * 256 + threadIdx.x;
    int bb = idx >> 19;
    int rem = idx & ((1 << 19) - 1);
    int c = rem >> 11;
    int l = rem & (L_DIMM - 1);
    int code = g_code[bb * L_DIMM + l];
    float v = __ldg(&cb[(size_t)code * C_DIMM + c]);
    emb_out[idx] = v;
    float d = x[idx] - v;
    sred[threadIdx.x] = d * d;
    __syncthreads();
    #pragma unroll
    for (int o = 128; o > 0; o >>= 1) {
        if (threadIdx.x < o) sred[threadIdx.x] += sred[threadIdx.x + o];
        __syncthreads();
    }
    if (threadIdx.x == 0) g_partial[blockIdx.x] = sred[0];
}

__global__ void finalize_kernel(float* __restrict__ loss_out) {
    __shared__ float sred[256];
    float s = 0.0f;
    for (int i = threadIdx.x; i < EMB_N / 256; i += 256) s += g_partial[i];
    sred[threadIdx.x] = s;
    __syncthreads();
    #pragma unroll
    for (int o = 128; o > 0; o >>= 1) {
        if (threadIdx.x < o) sred[threadIdx.x] += sred[threadIdx.x + o];
        __syncthreads();
    }
    if (threadIdx.x == 0) loss_out[0] = sred[0] * (1.0f / (float)EMB_N);
}

// ---------------- launch ----------------
extern "C" void kernel_launch(void* const* d_in, const int* in_sizes, int n_in,
                              void* d_out, int out_size) {
    const float* x  = (const float*)d_in[0];   // (8, 256, 2048)
    const float* cb = (const float*)d_in[1];   // (8192, 256)
    float* out = (float*)d_out;

    csq_kernel<<<K_CB / 8, 256>>>(cb);
    cmax_kernel<<<1, 256>>>();
    argmax_hf<<<M_DIM / BM, 256>>>(x, cb);
    rescue_kernel<<<M_DIM / 8, 256>>>(x, cb);

    const int full = M_DIM + EMB_N + 1;
    if (out_size >= full) {
        code_cast_kernel<<<(M_DIM + 255) / 256, 256>>>(out);
        gather_loss_kernel<<<EMB_N / 256, 256>>>(x, cb, out + M_DIM);
        finalize_kernel<<<1, 256>>>(out + M_DIM + EMB_N);
    } else if (out_size == EMB_N) {
        gather_loss_kernel<<<EMB_N / 256, 256>>>(x, cb, out);
    } else if (out_size == M_DIM) {
        code_cast_kernel<<<(M_DIM + 255) / 256, 256>>>(out);
    } else {
        gather_loss_kernel<<<EMB_N / 256, 256>>>(x, cb, out);
    }
}